// round 16
// baseline (speedup 1.0000x reference)
#include <cuda_runtime.h>

// VanillaRNN collapsed to a scalar recurrence c <- f(x_t, c),
//   f(x,c) = bh + sum_j Wh[j]*tanh(wx[j]*x + bx[j] + c).
// f tabulated 64(x, linear) x 192(c, cubic) as Catmull-Rom coefficients,
// 16B row pad. Round 16 = round 15 with the ring-prefetch overrun fixed:
// g_ring padded by 8 pairs (prefetch reads pairs up to 259; pad makes the
// dead loads legal). Build fully unrolled; ring CTAs fused into build.

#define BATCH   4096
#define SEQ     512
#define HID     2048
#define NOUT    10

#define TNX     64
#define TNC     192
#define IC4     (TNC / 4)                // 48
#define XMIN    (-8.0f)
#define USCALE  4.0f                     // TNX/16
#define VSCALE  12.0f                    // TNC/16
#define TH_C    (16.0f / TNC)
#define TH_X    (16.0f / TNX)
#define MAGIC   12582912.0f              // 2^23 + 2^22
#define MAGIC_B (MAGIC + 95.5f)          // folds v = 12c+96 and the -0.5
#define CLO     (-7.915f)                // keeps N in [1, 188]
#define CHI     ( 7.749f)
#define MAGIC_I 0x4B400000u              // bit pattern of MAGIC
#define ROWB    3088u                    // 192*16 + 16B pad

#define BUILD_CTAS 384
#define RING_CTAS  128
#define NPAIR      (SEQ / 2)             // 256 (su,row) pairs per batch elem
#define RING_PAD   8                     // prefetch overrun slack (pairs)

#define SCAN_SMEM  (TNX * 3088)          // 197632 B (padded coeff table / Wy)

__device__ float  g_scalar[TNX * TNC + 4];
__device__ float4 g_coeff[TNX * TNC];
__device__ float4 g_ring[(NPAIR + RING_PAD) * BATCH]; // (su0,row0,su1,row1)

__device__ __forceinline__ float tanh_hw(float v) {
    float r;
    asm("tanh.approx.f32 %0, %1;" : "=f"(r) : "f"(v));
    return r;
}

// ---------------- Kernel 1: build f table + x-side ring (fused) -----------
// CTAs [0, 384): table values, warp = (ix, ic0..ic0+3), fully unrolled.
// CTAs [384, 512): the (su, rowoff) ring — memory-bound, hides under MUFU.
__global__ __launch_bounds__(256)
void build_kernel(const float* __restrict__ Wx,
                  const float* __restrict__ bx,
                  const float* __restrict__ Wh,
                  const float* __restrict__ bhp,
                  const float* __restrict__ x)
{
    __shared__ float4 w[HID];            // (wx, bx, wh, -) : 32 KB
    const int tid = threadIdx.x;

    if (blockIdx.x >= BUILD_CTAS) {
        // ---- ring CTAs ----
        const int rb   = blockIdx.x - BUILD_CTAS;     // 0..127
        const int base = rb * ((NPAIR * BATCH) / RING_CTAS);   // 8192 each
        for (int i = tid; i < (NPAIR * BATCH) / RING_CTAS; i += 256) {
            int e  = base + i;
            int t2 = e >> 12;                         // / BATCH
            int b  = e & (BATCH - 1);
            float x0 = __ldg(&x[(2 * t2) * BATCH + b]);
            float x1 = __ldg(&x[(2 * t2 + 1) * BATCH + b]);

            float up0 = fmaf(x0, USCALE, 31.5f);
            up0 = fminf(fmaxf(up0, 0.5f), 62.499f);
            float tmx0 = up0 + MAGIC;
            float su0  = up0 + 0.5f - (tmx0 - MAGIC);
            unsigned R0 = ((unsigned)__float_as_int(tmx0) - MAGIC_I) * ROWB;

            float up1 = fmaf(x1, USCALE, 31.5f);
            up1 = fminf(fmaxf(up1, 0.5f), 62.499f);
            float tmx1 = up1 + MAGIC;
            float su1  = up1 + 0.5f - (tmx1 - MAGIC);
            unsigned R1 = ((unsigned)__float_as_int(tmx1) - MAGIC_I) * ROWB;

            g_ring[e] = make_float4(su0, __uint_as_float(R0),
                                    su1, __uint_as_float(R1));
        }
        return;
    }

    // ---- table CTAs ----
    for (int j = tid; j < HID; j += 256)
        w[j] = make_float4(__ldg(&Wx[j]), __ldg(&bx[j]), __ldg(&Wh[j]), 0.0f);
    __syncthreads();

    const int warp = tid >> 5;
    const int lane = tid & 31;
    const int unit = blockIdx.x * 8 + warp;       // 0 .. 3071
    const int ix   = unit / IC4;
    const int ic0  = (unit - ix * IC4) * 4;
    const float xv  = fmaf((float)ix,  TH_X, XMIN);
    const float cv0 = fmaf((float)ic0, TH_C, XMIN);
    const float cv1 = cv0 + TH_C;
    const float cv2 = cv0 + 2.0f * TH_C;
    const float cv3 = cv0 + 3.0f * TH_C;

    float a0 = 0.0f, a1 = 0.0f, a2 = 0.0f, a3 = 0.0f;
#pragma unroll
    for (int i = 0; i < HID / 32; i++) {          // fully unrolled: 64 iters
        float4 p = w[i * 32 + lane];              // constant-offset LDS.128
        float a  = fmaf(p.x, xv, p.y);
        a0 = fmaf(p.z, tanh_hw(a + cv0), a0);
        a1 = fmaf(p.z, tanh_hw(a + cv1), a1);
        a2 = fmaf(p.z, tanh_hw(a + cv2), a2);
        a3 = fmaf(p.z, tanh_hw(a + cv3), a3);
    }
#pragma unroll
    for (int off = 16; off; off >>= 1) {
        a0 += __shfl_xor_sync(0xffffffffu, a0, off);
        a1 += __shfl_xor_sync(0xffffffffu, a1, off);
        a2 += __shfl_xor_sync(0xffffffffu, a2, off);
        a3 += __shfl_xor_sync(0xffffffffu, a3, off);
    }
    if (lane == 0) {
        const float bh0 = bhp[0];
        *(float4*)&g_scalar[ix * TNC + ic0] =
            make_float4(a0 + bh0, a1 + bh0, a2 + bh0, a3 + bh0);
    }
}

// ---------------- Kernel 2: values -> Catmull-Rom coefficients ------------
__global__ __launch_bounds__(256)
void coeff_kernel()
{
    const int e = blockIdx.x * 256 + threadIdx.x;      // 0 .. 12287
    const int total = TNX * TNC;
    int im1 = (e - 1 < 0) ? 0 : e - 1;
    int ip1 = (e + 1 < total) ? e + 1 : total - 1;
    int ip2 = (e + 2 < total) ? e + 2 : total - 1;
    float p0 = g_scalar[im1];
    float p1 = g_scalar[e];
    float p2 = g_scalar[ip1];
    float p3 = g_scalar[ip2];
    float c0 = p1;
    float c1 = 0.5f * (p2 - p0);
    float c2 = p0 - 2.5f * p1 + 2.0f * p2 - 0.5f * p3;
    float c3 = fmaf(1.5f, p1 - p2, 0.5f * (p3 - p0));
    g_coeff[e] = make_float4(c0, c1, c2, c3);
}

// ---------------- Kernel 3: scan + fused epilogue ----------------
// 128 CTAs x 128 threads: copy coeffs into padded smem; warp 0 scans 32
// chains consuming the precomputed ring; then all threads reuse the smem
// for Wy/Wx/bx and run the epilogue.

#define STEP(I)                                                              \
    {                                                                        \
        float cc = fminf(fmaxf(c, CLO), CHI);                                \
        float tm = fmaf(cc, VSCALE, MAGIC_B);                                \
        unsigned addr = (unsigned)__float_as_int(tm) * 16u + rowK[I];        \
        float4 q0, q1;                                                       \
        asm volatile("ld.shared.v4.f32 {%0,%1,%2,%3}, [%4];"                 \
            : "=f"(q0.x), "=f"(q0.y), "=f"(q0.z), "=f"(q0.w) : "r"(addr));   \
        asm volatile("ld.shared.v4.f32 {%0,%1,%2,%3}, [%4];"                 \
            : "=f"(q1.x), "=f"(q1.y), "=f"(q1.z), "=f"(q1.w)                 \
            : "r"(addr + ROWB));                                             \
        float sv = fmaf(cc, VSCALE, 96.0f) - (tm - MAGIC);                   \
        float s2 = sv * sv;                                                  \
        float r0 = fmaf(s2, fmaf(q0.w, sv, q0.z), fmaf(q0.y, sv, q0.x));     \
        float r1 = fmaf(s2, fmaf(q1.w, sv, q1.z), fmaf(q1.y, sv, q1.x));     \
        c = fmaf(su[I], r1 - r0, r0);                                        \
    }

__global__ __launch_bounds__(128)
void scan_kernel(const float* __restrict__ x,     // (SEQ, BATCH)
                 const float* __restrict__ bhp,
                 const float* __restrict__ Wx,
                 const float* __restrict__ bxp,
                 const float* __restrict__ Wy,
                 const float* __restrict__ by,
                 float* __restrict__ out)
{
    extern __shared__ __align__(16) char smem[];  // table, then Wy/Wx/bx
    __shared__ float cfin[32];

    const int tid = threadIdx.x;
    for (int e = tid; e < TNX * TNC; e += 128) {
        int ix = e / TNC;
        int ic = e - ix * TNC;
        *(float4*)(smem + ix * 3088 + ic * 16) = __ldg(&g_coeff[e]);
    }
    __syncthreads();

    const int b0 = blockIdx.x * 32;

    if (tid < 32) {
        const int b = b0 + tid;
        const unsigned smem32 = (unsigned)__cvta_generic_to_shared(smem);
        const unsigned CBASE  = smem32 - MAGIC_I * 16u;
        const float4* rp = g_ring + b;            // stride BATCH per pair

        float c = bhp[0];                // c_0 = bh (h0 = 0)

        // Double-buffered 8-step blocks of ring data (4 float4 = 8 steps).
        float4 rb0[4], rb1[4];
#pragma unroll
        for (int q = 0; q < 4; q++) rb0[q] = __ldg(rp + q * BATCH);
#pragma unroll
        for (int q = 0; q < 4; q++) rb1[q] = __ldg(rp + (4 + q) * BATCH);

        float    su[8];
        unsigned rowK[8];

        for (int blk = 0; blk < 63; blk++) {
            // block+2's ring loads (dead on the last iterations; g_ring is
            // padded by RING_PAD pairs so the loads stay in-bounds)
            float4 rn[4];
#pragma unroll
            for (int q = 0; q < 4; q++)
                rn[q] = __ldg(rp + ((blk + 2) * 4 + q) * BATCH);
            // unpack current block (off-chain, cheap)
#pragma unroll
            for (int q = 0; q < 4; q++) {
                su[2 * q]       = rb0[q].x;
                rowK[2 * q]     = __float_as_uint(rb0[q].y) + CBASE;
                su[2 * q + 1]   = rb0[q].z;
                rowK[2 * q + 1] = __float_as_uint(rb0[q].w) + CBASE;
            }
#pragma unroll
            for (int i = 0; i < 8; i++) STEP(i);
#pragma unroll
            for (int q = 0; q < 4; q++) { rb0[q] = rb1[q]; rb1[q] = rn[q]; }
        }
        // tail: t = 504..510 (7 steps) from rb0
#pragma unroll
        for (int q = 0; q < 4; q++) {
            su[2 * q]       = rb0[q].x;
            rowK[2 * q]     = __float_as_uint(rb0[q].y) + CBASE;
            su[2 * q + 1]   = rb0[q].z;
            rowK[2 * q + 1] = __float_as_uint(rb0[q].w) + CBASE;
        }
#pragma unroll
        for (int i = 0; i < 7; i++) STEP(i);

        cfin[tid] = c;
    }
    __syncthreads();

    // --- epilogue: reuse smem for Wy/Wx/bx ---
    float* swy = (float*)smem;                    // 20480 floats
    float* swx = swy + NOUT * HID;                // 2048
    float* sbx = swx + HID;                       // 2048
    {
        const float4* wy4 = (const float4*)Wy;
        float4* d = (float4*)swy;
        for (int i = tid; i < (NOUT * HID) / 4; i += 128) d[i] = __ldg(&wy4[i]);
        const float4* wx4 = (const float4*)Wx;
        const float4* bx4 = (const float4*)bxp;
        float4* dx = (float4*)swx;
        float4* db = (float4*)sbx;
        for (int i = tid; i < HID / 4; i += 128) {
            dx[i] = __ldg(&wx4[i]);
            db[i] = __ldg(&bx4[i]);
        }
    }
    __syncthreads();

    const int warp = tid >> 5;
    const int lane = tid & 31;

    for (int g = 0; g < 2; g++) {                 // warp: 8 b's in 2 groups
        const int bb = b0 + warp * 8 + g * 4;

        float xt[4], cf[4];
#pragma unroll
        for (int i = 0; i < 4; i++) {
            xt[i] = __ldg(&x[(SEQ - 1) * BATCH + bb + i]);
            cf[i] = cfin[warp * 8 + g * 4 + i];
        }

        float lacc[4][NOUT];
#pragma unroll
        for (int i = 0; i < 4; i++)
#pragma unroll
            for (int o = 0; o < NOUT; o++) lacc[i][o] = 0.0f;

        for (int k = 0; k < 16; k++) {
            const int j = k * 128 + lane * 4;
            float4 wx4 = *(const float4*)(swx + j);
            float4 bx4 = *(const float4*)(sbx + j);
            float4 h[4];
#pragma unroll
            for (int i = 0; i < 4; i++) {
                h[i].x = tanh_hw(fmaf(wx4.x, xt[i], bx4.x) + cf[i]);
                h[i].y = tanh_hw(fmaf(wx4.y, xt[i], bx4.y) + cf[i]);
                h[i].z = tanh_hw(fmaf(wx4.z, xt[i], bx4.z) + cf[i]);
                h[i].w = tanh_hw(fmaf(wx4.w, xt[i], bx4.w) + cf[i]);
            }
#pragma unroll
            for (int o = 0; o < NOUT; o++) {
                float4 wy4 = *(const float4*)(swy + o * HID + j);
#pragma unroll
                for (int i = 0; i < 4; i++)
                    lacc[i][o] = fmaf(wy4.x, h[i].x, fmaf(wy4.y, h[i].y,
                                 fmaf(wy4.z, h[i].z, fmaf(wy4.w, h[i].w, lacc[i][o]))));
            }
        }

#pragma unroll
        for (int i = 0; i < 4; i++)
#pragma unroll
            for (int o = 0; o < NOUT; o++) {
                float v = lacc[i][o];
#pragma unroll
                for (int off = 16; off; off >>= 1)
                    v += __shfl_xor_sync(0xffffffffu, v, off);
                lacc[i][o] = v;
            }

        if (lane == 0) {
#pragma unroll
            for (int i = 0; i < 4; i++) {
                float logits[NOUT];
                float mx = -1e30f;
#pragma unroll
                for (int o = 0; o < NOUT; o++) {
                    logits[o] = lacc[i][o] + __ldg(&by[o]);
                    mx = fmaxf(mx, logits[o]);
                }
                float den = 0.0f;
#pragma unroll
                for (int o = 0; o < NOUT; o++) {
                    logits[o] = __expf(logits[o] - mx);
                    den += logits[o];
                }
                float inv = 1.0f / den;
#pragma unroll
                for (int o = 0; o < NOUT; o++)
                    out[(bb + i) * NOUT + o] = logits[o] * inv;
            }
        }
    }
}

extern "C" void kernel_launch(void* const* d_in, const int* in_sizes, int n_in,
                              void* d_out, int out_size)
{
    const float* x   = (const float*)d_in[0];  // (512, 4096)
    const float* Wx  = (const float*)d_in[1];  // (2048, 1)
    const float* bx  = (const float*)d_in[2];  // (2048,)
    const float* Wh  = (const float*)d_in[3];  // (1, 2048)
    const float* bh  = (const float*)d_in[4];  // (1,)
    const float* Wy  = (const float*)d_in[5];  // (10, 2048)
    const float* by  = (const float*)d_in[6];  // (10,)
    float* out = (float*)d_out;                // (4096, 10)

    cudaFuncSetAttribute(scan_kernel,
                         cudaFuncAttributeMaxDynamicSharedMemorySize, SCAN_SMEM);

    build_kernel<<<BUILD_CTAS + RING_CTAS, 256>>>(Wx, bx, Wh, bh, x);
    coeff_kernel<<<(TNX * TNC) / 256, 256>>>();                 // 48 CTAs
    scan_kernel<<<BATCH / 32, 128, SCAN_SMEM>>>(x, bh, Wx, bx, Wy, by, out);
}

// round 17
// speedup vs baseline: 1.1067x; 1.1067x over previous
#include <cuda_runtime.h>

// VanillaRNN collapsed to a scalar recurrence c <- f(x_t, c),
//   f(x,c) = bh + sum_j Wh[j]*tanh(wx[j]*x + bx[j] + c).
// f tabulated 64(x, linear) x 192(c, cubic) as Catmull-Rom coefficients,
// 16B row pad (bank-group decollision). Round 17: round-14 structure
// (ring reverted — it regressed), scan kernel widened to 256 threads for
// 2x pack/staging MLP and a one-pass epilogue (8 warps x 4 b).

#define BATCH   4096
#define SEQ     512
#define HID     2048
#define NOUT    10

#define TNX     64
#define TNC     192
#define IC4     (TNC / 4)                // 48
#define XMIN    (-8.0f)
#define USCALE  4.0f                     // TNX/16
#define VSCALE  12.0f                    // TNC/16
#define TH_C    (16.0f / TNC)
#define TH_X    (16.0f / TNX)
#define MAGIC   12582912.0f              // 2^23 + 2^22
#define MAGIC_B (MAGIC + 95.5f)          // folds v = 12c+96 and the -0.5
#define CLO     (-7.915f)                // keeps N in [1, 188]
#define CHI     ( 7.749f)
#define MAGIC_I 0x4B400000u              // bit pattern of MAGIC
#define ROWB    3088u                    // 192*16 + 16B pad

#define SCAN_SMEM  (TNX * 3088)          // 197632 B (padded coeff table / Wy)

__device__ float  g_scalar[TNX * TNC + 4];
__device__ float4 g_coeff[TNX * TNC];

__device__ __forceinline__ float tanh_hw(float v) {
    float r;
    asm("tanh.approx.f32 %0, %1;" : "=f"(r) : "f"(v));
    return r;
}

// ---------------- Kernel 1: build f table (values) ----------------
// 384 CTAs x 256 threads; warp = one (ix, ic0..ic0+3) unit, conflict-free LDS.
__global__ __launch_bounds__(256)
void build_kernel(const float* __restrict__ Wx,
                  const float* __restrict__ bx,
                  const float* __restrict__ Wh,
                  const float* __restrict__ bhp)
{
    __shared__ float4 w[HID];            // (wx, bx, wh, -) : 32 KB
    const int tid = threadIdx.x;
    for (int j = tid; j < HID; j += 256)
        w[j] = make_float4(__ldg(&Wx[j]), __ldg(&bx[j]), __ldg(&Wh[j]), 0.0f);
    __syncthreads();

    const int warp = tid >> 5;
    const int lane = tid & 31;
    const int unit = blockIdx.x * 8 + warp;       // 0 .. 3071
    const int ix   = unit / IC4;
    const int ic0  = (unit - ix * IC4) * 4;
    const float xv  = fmaf((float)ix,  TH_X, XMIN);
    const float cv0 = fmaf((float)ic0, TH_C, XMIN);
    const float cv1 = cv0 + TH_C;
    const float cv2 = cv0 + 2.0f * TH_C;
    const float cv3 = cv0 + 3.0f * TH_C;

    float a0 = 0.0f, a1 = 0.0f, a2 = 0.0f, a3 = 0.0f;
#pragma unroll 4
    for (int i = 0; i < HID / 32; i++) {
        float4 p = w[i * 32 + lane];              // consecutive across lanes
        float a  = fmaf(p.x, xv, p.y);
        a0 = fmaf(p.z, tanh_hw(a + cv0), a0);
        a1 = fmaf(p.z, tanh_hw(a + cv1), a1);
        a2 = fmaf(p.z, tanh_hw(a + cv2), a2);
        a3 = fmaf(p.z, tanh_hw(a + cv3), a3);
    }
#pragma unroll
    for (int off = 16; off; off >>= 1) {
        a0 += __shfl_xor_sync(0xffffffffu, a0, off);
        a1 += __shfl_xor_sync(0xffffffffu, a1, off);
        a2 += __shfl_xor_sync(0xffffffffu, a2, off);
        a3 += __shfl_xor_sync(0xffffffffu, a3, off);
    }
    if (lane == 0) {
        const float bh0 = bhp[0];
        *(float4*)&g_scalar[ix * TNC + ic0] =
            make_float4(a0 + bh0, a1 + bh0, a2 + bh0, a3 + bh0);
    }
}

// ---------------- Kernel 2: values -> Catmull-Rom coefficients ------------
__global__ __launch_bounds__(256)
void coeff_kernel()
{
    const int e = blockIdx.x * 256 + threadIdx.x;      // 0 .. 12287
    const int total = TNX * TNC;
    int im1 = (e - 1 < 0) ? 0 : e - 1;
    int ip1 = (e + 1 < total) ? e + 1 : total - 1;
    int ip2 = (e + 2 < total) ? e + 2 : total - 1;
    float p0 = g_scalar[im1];
    float p1 = g_scalar[e];
    float p2 = g_scalar[ip1];
    float p3 = g_scalar[ip2];
    float c0 = p1;
    float c1 = 0.5f * (p2 - p0);
    float c2 = p0 - 2.5f * p1 + 2.0f * p2 - 0.5f * p3;
    float c3 = fmaf(1.5f, p1 - p2, 0.5f * (p3 - p0));
    g_coeff[e] = make_float4(c0, c1, c2, c3);
}

// ---------------- Kernel 3: scan + fused epilogue (256 threads) -----------
// 128 CTAs x 256 threads: all threads pack coeffs into padded smem; warp 0
// scans 32 chains; then all 8 warps reuse the smem for Wy/Wx/bx and run a
// one-pass epilogue (warp w handles 4 batch elements).

#define STEP(I)                                                              \
    {                                                                        \
        float cc = fminf(fmaxf(c, CLO), CHI);                                \
        float tm = fmaf(cc, VSCALE, MAGIC_B);                                \
        unsigned addr = (unsigned)__float_as_int(tm) * 16u + K[I];           \
        float4 q0, q1;                                                       \
        asm volatile("ld.shared.v4.f32 {%0,%1,%2,%3}, [%4];"                 \
            : "=f"(q0.x), "=f"(q0.y), "=f"(q0.z), "=f"(q0.w) : "r"(addr));   \
        asm volatile("ld.shared.v4.f32 {%0,%1,%2,%3}, [%4];"                 \
            : "=f"(q1.x), "=f"(q1.y), "=f"(q1.z), "=f"(q1.w)                 \
            : "r"(addr + ROWB));                                             \
        float sv = fmaf(cc, VSCALE, 96.0f) - (tm - MAGIC);                   \
        float s2 = sv * sv;                                                  \
        float r0 = fmaf(s2, fmaf(q0.w, sv, q0.z), fmaf(q0.y, sv, q0.x));     \
        float r1 = fmaf(s2, fmaf(q1.w, sv, q1.z), fmaf(q1.y, sv, q1.x));     \
        c = fmaf(su[I], r1 - r0, r0);                                        \
    }

#define XSIDE(I, XV)                                                         \
    {                                                                        \
        float up = fmaf((XV), USCALE, 31.5f);                                \
        up = fminf(fmaxf(up, 0.5f), 62.499f);                                \
        float tmx = up + MAGIC;                                              \
        su[I] = up + 0.5f - (tmx - MAGIC);                                   \
        K[I]  = (unsigned)__float_as_int(tmx) * ROWB + KBASE;                \
    }

__global__ __launch_bounds__(256)
void scan_kernel(const float* __restrict__ x,     // (SEQ, BATCH)
                 const float* __restrict__ bhp,
                 const float* __restrict__ Wx,
                 const float* __restrict__ bxp,
                 const float* __restrict__ Wy,
                 const float* __restrict__ by,
                 float* __restrict__ out)
{
    extern __shared__ __align__(16) char smem[];  // table, then Wy/Wx/bx
    __shared__ float cfin[32];

    const int tid = threadIdx.x;
    for (int e = tid; e < TNX * TNC; e += 256) {
        int ix = e / TNC;
        int ic = e - ix * TNC;
        *(float4*)(smem + ix * 3088 + ic * 16) = __ldg(&g_coeff[e]);
    }
    __syncthreads();

    const int b0 = blockIdx.x * 32;

    if (tid < 32) {
        const int b = b0 + tid;
        const unsigned smem32 = (unsigned)__cvta_generic_to_shared(smem);
        const unsigned KBASE  = smem32 - MAGIC_I * ROWB - MAGIC_I * 16u;

        float c = bhp[0];                // c_0 = bh (h0 = 0)

        float xb0[8], xb1[8];
#pragma unroll
        for (int i = 0; i < 8; i++) xb0[i] = __ldg(&x[i * BATCH + b]);
#pragma unroll
        for (int i = 0; i < 8; i++) xb1[i] = __ldg(&x[(8 + i) * BATCH + b]);

        float    su[8];
        unsigned K[8];

        for (int blk = 0; blk < 63; blk++) {
            float xn[8];
#pragma unroll
            for (int i = 0; i < 8; i++) {
                int tt = (blk + 2) * 8 + i;
                xn[i] = (tt < SEQ) ? __ldg(&x[tt * BATCH + b]) : 0.0f;
            }
#pragma unroll
            for (int i = 0; i < 8; i++) XSIDE(i, xb0[i]);
#pragma unroll
            for (int i = 0; i < 8; i++) STEP(i);
#pragma unroll
            for (int i = 0; i < 8; i++) { xb0[i] = xb1[i]; xb1[i] = xn[i]; }
        }
#pragma unroll
        for (int i = 0; i < 7; i++) XSIDE(i, xb0[i]);
#pragma unroll
        for (int i = 0; i < 7; i++) STEP(i);

        cfin[tid] = c;
    }
    __syncthreads();

    // --- epilogue: reuse smem for Wy/Wx/bx ---
    float* swy = (float*)smem;                    // 20480 floats
    float* swx = swy + NOUT * HID;                // 2048
    float* sbx = swx + HID;                       // 2048
    {
        const float4* wy4 = (const float4*)Wy;
        float4* d = (float4*)swy;
        for (int i = tid; i < (NOUT * HID) / 4; i += 256) d[i] = __ldg(&wy4[i]);
        const float4* wx4 = (const float4*)Wx;
        const float4* bx4 = (const float4*)bxp;
        float4* dx = (float4*)swx;
        float4* db = (float4*)sbx;
        for (int i = tid; i < HID / 4; i += 256) {
            dx[i] = __ldg(&wx4[i]);
            db[i] = __ldg(&bx4[i]);
        }
    }
    __syncthreads();

    const int warp = tid >> 5;
    const int lane = tid & 31;
    const int bb   = b0 + warp * 4;               // 8 warps x 4 b = 32 b

    float xt[4], cf[4];
#pragma unroll
    for (int i = 0; i < 4; i++) {
        xt[i] = __ldg(&x[(SEQ - 1) * BATCH + bb + i]);
        cf[i] = cfin[warp * 4 + i];
    }

    float lacc[4][NOUT];
#pragma unroll
    for (int i = 0; i < 4; i++)
#pragma unroll
        for (int o = 0; o < NOUT; o++) lacc[i][o] = 0.0f;

    for (int k = 0; k < 16; k++) {
        const int j = k * 128 + lane * 4;
        float4 wx4 = *(const float4*)(swx + j);
        float4 bx4 = *(const float4*)(sbx + j);
        float4 h[4];
#pragma unroll
        for (int i = 0; i < 4; i++) {
            h[i].x = tanh_hw(fmaf(wx4.x, xt[i], bx4.x) + cf[i]);
            h[i].y = tanh_hw(fmaf(wx4.y, xt[i], bx4.y) + cf[i]);
            h[i].z = tanh_hw(fmaf(wx4.z, xt[i], bx4.z) + cf[i]);
            h[i].w = tanh_hw(fmaf(wx4.w, xt[i], bx4.w) + cf[i]);
        }
#pragma unroll
        for (int o = 0; o < NOUT; o++) {
            float4 wy4 = *(const float4*)(swy + o * HID + j);
#pragma unroll
            for (int i = 0; i < 4; i++)
                lacc[i][o] = fmaf(wy4.x, h[i].x, fmaf(wy4.y, h[i].y,
                             fmaf(wy4.z, h[i].z, fmaf(wy4.w, h[i].w, lacc[i][o]))));
        }
    }

#pragma unroll
    for (int i = 0; i < 4; i++)
#pragma unroll
        for (int o = 0; o < NOUT; o++) {
            float v = lacc[i][o];
#pragma unroll
            for (int off = 16; off; off >>= 1)
                v += __shfl_xor_sync(0xffffffffu, v, off);
            lacc[i][o] = v;
        }

    if (lane == 0) {
#pragma unroll
        for (int i = 0; i < 4; i++) {
            float logits[NOUT];
            float mx = -1e30f;
#pragma unroll
            for (int o = 0; o < NOUT; o++) {
                logits[o] = lacc[i][o] + __ldg(&by[o]);
                mx = fmaxf(mx, logits[o]);
            }
            float den = 0.0f;
#pragma unroll
            for (int o = 0; o < NOUT; o++) {
                logits[o] = __expf(logits[o] - mx);
                den += logits[o];
            }
            float inv = 1.0f / den;
#pragma unroll
            for (int o = 0; o < NOUT; o++)
                out[(bb + i) * NOUT + o] = logits[o] * inv;
        }
    }
}

extern "C" void kernel_launch(void* const* d_in, const int* in_sizes, int n_in,
                              void* d_out, int out_size)
{
    const float* x   = (const float*)d_in[0];  // (512, 4096)
    const float* Wx  = (const float*)d_in[1];  // (2048, 1)
    const float* bx  = (const float*)d_in[2];  // (2048,)
    const float* Wh  = (const float*)d_in[3];  // (1, 2048)
    const float* bh  = (const float*)d_in[4];  // (1,)
    const float* Wy  = (const float*)d_in[5];  // (10, 2048)
    const float* by  = (const float*)d_in[6];  // (10,)
    float* out = (float*)d_out;                // (4096, 10)

    cudaFuncSetAttribute(scan_kernel,
                         cudaFuncAttributeMaxDynamicSharedMemorySize, SCAN_SMEM);

    build_kernel<<<(TNX * IC4) / 8, 256>>>(Wx, bx, Wh, bh);     // 384 CTAs
    coeff_kernel<<<(TNX * TNC) / 256, 256>>>();                 // 48 CTAs
    scan_kernel<<<BATCH / 32, 256, SCAN_SMEM>>>(x, bh, Wx, bx, Wy, by, out);
}